// round 3
// baseline (speedup 1.0000x reference)
#include <cuda_runtime.h>
#include <cstdint>

namespace {

constexpr int KNUM  = 32;           // pole pairs
constexpr int KP    = 16;           // packed pairs-of-poles (f32x2 lanes)
constexpr int DDIM  = 1024;
constexpr int LLEN  = 2048;
constexpr int CHUNK = 128;          // output elements per thread

using u64 = unsigned long long;

// ---- packed f32x2 primitives (sm_103a dual-issue fp32 path) ----
__device__ __forceinline__ u64 pk2(float lo, float hi) {
    u64 r; asm("mov.b64 %0, {%1, %2};" : "=l"(r) : "f"(lo), "f"(hi)); return r;
}
__device__ __forceinline__ void unpk2(u64 v, float& lo, float& hi) {
    asm("mov.b64 {%0, %1}, %2;" : "=f"(lo), "=f"(hi) : "l"(v));
}
__device__ __forceinline__ u64 add2(u64 a, u64 b) {
    u64 d; asm("add.rn.f32x2 %0, %1, %2;" : "=l"(d) : "l"(a), "l"(b)); return d;
}
__device__ __forceinline__ u64 mul2(u64 a, u64 b) {
    u64 d; asm("mul.rn.f32x2 %0, %1, %2;" : "=l"(d) : "l"(a), "l"(b)); return d;
}
__device__ __forceinline__ u64 fma2(u64 a, u64 b, u64 c) {
    u64 d; asm("fma.rn.f32x2 %0, %1, %2, %3;" : "=l"(d) : "l"(a), "l"(b), "l"(c)); return d;
}

// Each warp: 2 rows (d), 16 chunks of 128 t-steps each (one chunk per lane-half).
// Per thread state: 16 f32x2 pairs of {a, b, x(t), x(t-1)} = 128 fp32 registers.
// Recurrence per pole: x(t+1) = a*x(t) + b*x(t-1), a = 2 r cos(theta), b = -r^2.
// Chunk starts re-anchored from closed form so error never accumulates past 128 steps.
__global__ void __launch_bounds__(128, 1)
modal_filter_kernel(const float* __restrict__ rr_,
                    const float* __restrict__ th_,
                    const float* __restrict__ Rre_,
                    const float* __restrict__ Rim_,
                    const float* __restrict__ h0_,
                    float* __restrict__ out)
{
    const int tid  = threadIdx.x;
    const int wrp  = tid >> 5;
    const int lane = tid & 31;
    const int dh   = lane >> 4;          // which of the warp's 2 rows
    const int c    = lane & 15;          // chunk index within row
    const int d    = (blockIdx.x * 4 + wrp) * 2 + dh;

    // Output window [128c, 128c+128). Output j maps to series index t = j-1
    // (j = 0 is h_0). So this chunk's series starts at t0 = 128c - 1.
    const int    t0i = CHUNK * c - 1;
    const float  t0f = (float)t0i;
    const double t0d = (double)t0i;

    u64 A[KP], B[KP], X[KP], XM[KP];

    #pragma unroll
    for (int kp = 0; kp < KP; kp++) {
        float av[2], bv[2], x0[2], x1[2];
        #pragma unroll
        for (int j = 0; j < 2; j++) {
            const int k = kp * 2 + j;
            const float rv = __ldg(&rr_ [k * DDIM + d]);
            const float tv = __ldg(&th_ [k * DDIM + d]);
            const float Rr = __ldg(&Rre_[k * DDIM + d]);
            const float Ri = __ldg(&Rim_[k * DDIM + d]);

            float sT, cT;
            sincosf(tv, &sT, &cT);               // precise: feeds recurrence coeffs
            const float pre = rv * cT;
            const float pim = rv * sT;
            av[j] = pre + pre;                   // 2 r cos(theta)
            bv[j] = -(rv * rv);                  // -r^2

            // Closed-form anchor: amp = r^t0 (precise log/exp), phase = t0*theta
            // reduced mod 2pi in double so large-t phase stays ~1e-6 rad accurate.
            const float amp = expf(t0f * logf(rv));
            const double da = t0d * (double)tv;
            const double nn = floor(da * 0.15915494309189535);
            const float red = (float)fma(nn, -6.283185307179586, da);
            float sA, cA;
            __sincosf(red, &sA, &cA);            // small reduced arg: fast path OK

            const float wre = amp * (Rr * cA - Ri * sA);   // Re(R p^t0)
            const float wim = amp * (Rr * sA + Ri * cA);   // Im(R p^t0)
            x0[j] = wre;                                   // x(t0)
            x1[j] = wre * pre - wim * pim;                 // x(t0+1) = Re(R p^{t0+1})
        }
        A[kp]  = pk2(av[0], av[1]);
        B[kp]  = pk2(bv[0], bv[1]);
        XM[kp] = pk2(x0[0], x0[1]);
        X[kp]  = pk2(x1[0], x1[1]);
    }

    float* op = out + (size_t)d * LLEN + c * CHUNK;
    const float h0d = h0_[d];

    #pragma unroll 1
    for (int i = 0; i < CHUNK; i += 4) {
        float buf[4];
        #pragma unroll
        for (int j = 0; j < 4; j++) {
            // h(t) = sum_k x_k(t): 4-way accumulator tree over 16 pairs
            u64 a0 = XM[0], a1 = XM[1], a2 = XM[2], a3 = XM[3];
            #pragma unroll
            for (int kp = 4; kp < KP; kp += 4) {
                a0 = add2(a0, XM[kp + 0]);
                a1 = add2(a1, XM[kp + 1]);
                a2 = add2(a2, XM[kp + 2]);
                a3 = add2(a3, XM[kp + 3]);
            }
            const u64 s = add2(add2(a0, a1), add2(a2, a3));
            float lo, hi; unpk2(s, lo, hi);
            buf[j] = lo + hi;

            // advance all 32 recurrences (16 packed pairs): 2 f32x2 ops each
            #pragma unroll
            for (int kp = 0; kp < KP; kp++) {
                const u64 xn = fma2(A[kp], X[kp], mul2(B[kp], XM[kp]));
                XM[kp] = X[kp];
                X[kp]  = xn;
            }
        }
        if (i == 0 && c == 0) buf[0] = h0d;   // output position j=0 is h_0[d]
        float4 v; v.x = buf[0]; v.y = buf[1]; v.z = buf[2]; v.w = buf[3];
        *reinterpret_cast<float4*>(op + i) = v;   // 16B aligned: 128c + 4i
    }
}

} // namespace

extern "C" void kernel_launch(void* const* d_in, const int* in_sizes, int n_in,
                              void* d_out, int out_size) {
    const float* rr  = (const float*)d_in[0];   // r      (K, D)
    const float* th  = (const float*)d_in[1];   // theta  (K, D)
    const float* Rre = (const float*)d_in[2];   // R_re   (K, D)
    const float* Rim = (const float*)d_in[3];   // R_im   (K, D)
    const float* h0  = (const float*)d_in[4];   // h_0    (1, D)
    (void)in_sizes; (void)n_in; (void)out_size; // shapes fixed: K=32, D=1024, L=2048

    // 128 blocks x 128 threads = 512 warps; each warp covers 2 rows x 16 chunks.
    modal_filter_kernel<<<DDIM / 8, 128>>>(rr, th, Rre, Rim, h0, (float*)d_out);
}

// round 5
// speedup vs baseline: 1.4804x; 1.4804x over previous
#include <cuda_runtime.h>
#include <cstdint>

namespace {

constexpr int KNUM  = 32;           // pole pairs
constexpr int KP    = 16;           // packed pairs-of-poles (f32x2 lanes)
constexpr int DDIM  = 1024;
constexpr int LLEN  = 2048;
constexpr int CHUNK = 32;           // output elements per thread
constexpr int NCH   = LLEN / CHUNK; // 64 chunks per row

using u64 = unsigned long long;

// ---- packed f32x2 primitives (sm_103a dual-lane fp32 path) ----
__device__ __forceinline__ u64 pk2(float lo, float hi) {
    u64 r; asm("mov.b64 %0, {%1, %2};" : "=l"(r) : "f"(lo), "f"(hi)); return r;
}
__device__ __forceinline__ void unpk2(u64 v, float& lo, float& hi) {
    asm("mov.b64 {%0, %1}, %2;" : "=f"(lo), "=f"(hi) : "l"(v));
}
__device__ __forceinline__ u64 add2(u64 a, u64 b) {
    u64 d; asm("add.rn.f32x2 %0, %1, %2;" : "=l"(d) : "l"(a), "l"(b)); return d;
}
__device__ __forceinline__ u64 mul2(u64 a, u64 b) {
    u64 d; asm("mul.rn.f32x2 %0, %1, %2;" : "=l"(d) : "l"(a), "l"(b)); return d;
}
__device__ __forceinline__ u64 fma2(u64 a, u64 b, u64 c) {
    u64 d; asm("fma.rn.f32x2 %0, %1, %2, %3;" : "=l"(d) : "l"(a), "l"(b), "l"(c)); return d;
}
__device__ __forceinline__ float fast_lg2(float x) {
    float y; asm("lg2.approx.f32 %0, %1;" : "=f"(y) : "f"(x)); return y;
}
__device__ __forceinline__ float fast_ex2(float x) {
    float y; asm("ex2.approx.f32 %0, %1;" : "=f"(y) : "f"(x)); return y;
}

// One thread = one (d, chunk): 32 output taps. A warp's 32 lanes share one d
// (uniform/broadcast init loads) and cover 32 consecutive chunks of that row.
// Recurrence per pole: x(t+1) = a*x(t) + b*x(t-1), a = 2 r cos(theta), b = -r^2,
// packed 2 poles per f32x2. Chunk starts re-anchored from closed form (all-float,
// exact twoprod + Cody-Waite phase reduction) so error never accumulates >32 steps.
__global__ void __launch_bounds__(128)
modal_filter_kernel(const float* __restrict__ rr_,
                    const float* __restrict__ th_,
                    const float* __restrict__ Rre_,
                    const float* __restrict__ Rim_,
                    const float* __restrict__ h0_,
                    float* __restrict__ out)
{
    const int gtid = blockIdx.x * 128 + threadIdx.x;
    const int c    = gtid & (NCH - 1);   // chunk index within row (0..63)
    const int d    = gtid >> 6;          // channel row (uniform per warp)

    // Output window [32c, 32c+32). Output j maps to series index t = j-1
    // (j = 0 is h_0), so this chunk's series starts at t0 = 32c - 1.
    const float t0f = (float)(CHUNK * c - 1);

    u64 A[KP], B[KP], X[KP], XM[KP];

    #pragma unroll
    for (int kp = 0; kp < KP; kp++) {
        float av[2], bv[2], x0[2], x1[2];
        #pragma unroll
        for (int j = 0; j < 2; j++) {
            const int k = kp * 2 + j;
            const float rv = __ldg(&rr_ [k * DDIM + d]);
            const float tv = __ldg(&th_ [k * DDIM + d]);
            const float Rr = __ldg(&Rre_[k * DDIM + d]);
            const float Ri = __ldg(&Rim_[k * DDIM + d]);

            float sT, cT;
            __sincosf(tv, &sT, &cT);             // arg in [0, 2pi): fast path fine
            const float pre = rv * cT;
            const float pim = rv * sT;
            av[j] = pre + pre;                   // 2 r cos(theta)
            bv[j] = -(rv * rv);                  // -r^2

            // amp = r^t0 via MUFU lg2/ex2. Exponent abs err <= |t0|*2^-22:
            // only meaningful where amp ~1 (small t0) -> <1e-5 output impact.
            const float amp = fast_ex2(t0f * fast_lg2(rv));

            // phase = t0*theta mod 2pi, all-float: exact twoprod, then 2-constant
            // Cody-Waite. Residual ~1e-6 rad.
            const float hi = t0f * tv;
            const float lo = __fmaf_rn(t0f, tv, -hi);     // exact residual
            const float nn = rintf(hi * 0.15915494309f);  // 1/(2pi)
            float red = __fmaf_rn(nn, -6.28125f, hi);     // 2pi hi (13-bit exact)
            red = __fmaf_rn(nn, -1.9353071795864769e-3f, red); // 2pi - 6.28125
            red += lo;
            float sA, cA;
            __sincosf(red, &sA, &cA);

            const float wre = amp * (Rr * cA - Ri * sA);   // Re(R p^t0)
            const float wim = amp * (Rr * sA + Ri * cA);   // Im(R p^t0)
            x0[j] = wre;                                   // x(t0)
            x1[j] = wre * pre - wim * pim;                 // x(t0+1)
        }
        A[kp]  = pk2(av[0], av[1]);
        B[kp]  = pk2(bv[0], bv[1]);
        XM[kp] = pk2(x0[0], x0[1]);
        X[kp]  = pk2(x1[0], x1[1]);
    }

    float* op = out + (size_t)d * LLEN + c * CHUNK;
    const float h0d = h0_[d];

    #pragma unroll 1
    for (int i = 0; i < CHUNK; i += 4) {
        float buf[4];
        #pragma unroll
        for (int j = 0; j < 4; j++) {
            // h(t) = sum_k x_k(t): pairwise tree over 16 packed pairs
            u64 s01 = add2(XM[0],  XM[1]),  s23 = add2(XM[2],  XM[3]);
            u64 s45 = add2(XM[4],  XM[5]),  s67 = add2(XM[6],  XM[7]);
            u64 s89 = add2(XM[8],  XM[9]),  sAB = add2(XM[10], XM[11]);
            u64 sCD = add2(XM[12], XM[13]), sEF = add2(XM[14], XM[15]);
            u64 q0 = add2(s01, s23), q1 = add2(s45, s67);
            u64 q2 = add2(s89, sAB), q3 = add2(sCD, sEF);
            const u64 s = add2(add2(q0, q1), add2(q2, q3));
            float slo, shi; unpk2(s, slo, shi);
            buf[j] = slo + shi;

            // advance all 32 recurrences (16 packed pairs)
            #pragma unroll
            for (int kp = 0; kp < KP; kp++) {
                const u64 xn = fma2(A[kp], X[kp], mul2(B[kp], XM[kp]));
                XM[kp] = X[kp];
                X[kp]  = xn;
            }
        }
        if (i == 0 && c == 0) buf[0] = h0d;   // output position j=0 is h_0[d]
        float4 v; v.x = buf[0]; v.y = buf[1]; v.z = buf[2]; v.w = buf[3];
        *reinterpret_cast<float4*>(op + i) = v;   // 16B aligned: 32c + 4i
    }
}

} // namespace

extern "C" void kernel_launch(void* const* d_in, const int* in_sizes, int n_in,
                              void* d_out, int out_size) {
    const float* rr  = (const float*)d_in[0];   // r      (K, D)
    const float* th  = (const float*)d_in[1];   // theta  (K, D)
    const float* Rre = (const float*)d_in[2];   // R_re   (K, D)
    const float* Rim = (const float*)d_in[3];   // R_im   (K, D)
    const float* h0  = (const float*)d_in[4];   // h_0    (1, D)
    (void)in_sizes; (void)n_in; (void)out_size; // shapes fixed: K=32, D=1024, L=2048

    // 1024 rows x 64 chunks = 65536 threads = 2048 warps -> ~3.5 warps/SMSP
    modal_filter_kernel<<<(DDIM * NCH) / 128, 128>>>(
        rr, th, Rre, Rim, h0, (float*)d_out);
}

// round 6
// speedup vs baseline: 1.7069x; 1.1530x over previous
#include <cuda_runtime.h>
#include <cstdint>

namespace {

constexpr int KNUM  = 32;           // pole pairs total
constexpr int KP    = 8;            // packed pairs-of-poles per THREAD (16 poles)
constexpr int DDIM  = 1024;
constexpr int LLEN  = 2048;
constexpr int CHUNK = 32;           // output elements per chunk
constexpr int NCH   = LLEN / CHUNK; // 64 chunks per row

using u64 = unsigned long long;

// ---- packed f32x2 primitives (sm_103a dual-lane fp32 path) ----
__device__ __forceinline__ u64 pk2(float lo, float hi) {
    u64 r; asm("mov.b64 %0, {%1, %2};" : "=l"(r) : "f"(lo), "f"(hi)); return r;
}
__device__ __forceinline__ void unpk2(u64 v, float& lo, float& hi) {
    asm("mov.b64 {%0, %1}, %2;" : "=f"(lo), "=f"(hi) : "l"(v));
}
__device__ __forceinline__ u64 add2(u64 a, u64 b) {
    u64 d; asm("add.rn.f32x2 %0, %1, %2;" : "=l"(d) : "l"(a), "l"(b)); return d;
}
__device__ __forceinline__ u64 mul2(u64 a, u64 b) {
    u64 d; asm("mul.rn.f32x2 %0, %1, %2;" : "=l"(d) : "l"(a), "l"(b)); return d;
}
__device__ __forceinline__ u64 fma2(u64 a, u64 b, u64 c) {
    u64 d; asm("fma.rn.f32x2 %0, %1, %2, %3;" : "=l"(d) : "l"(a), "l"(b), "l"(c)); return d;
}
__device__ __forceinline__ float fast_lg2(float x) {
    float y; asm("lg2.approx.f32 %0, %1;" : "=f"(y) : "f"(x)); return y;
}
__device__ __forceinline__ float fast_ex2(float x) {
    float y; asm("ex2.approx.f32 %0, %1;" : "=f"(y) : "f"(x)); return y;
}

// Split-K decomposition: warp = (d, 16 chunks). Lane l: chunk c = cbase + (l&15),
// pole half = l>>4 (8 packed pairs = 16 poles per thread). Partner lanes (l ^ 16)
// share the chunk; one shfl_xor+add per output merges the two 16-pole partials.
// Recurrence per pole: x(t+1) = a*x(t) + b*x(t-1), a = 2 r cos(theta), b = -r^2,
// packed 2 poles per f32x2. Chunk starts re-anchored from closed form (all-float,
// exact twoprod + Cody-Waite phase reduction) so error never accumulates >32 steps.
__global__ void __launch_bounds__(128, 4)
modal_filter_kernel(const float* __restrict__ rr_,
                    const float* __restrict__ th_,
                    const float* __restrict__ Rre_,
                    const float* __restrict__ Rim_,
                    const float* __restrict__ h0_,
                    float* __restrict__ out)
{
    const int gtid = blockIdx.x * 128 + threadIdx.x;
    const int warp = gtid >> 5;
    const int lane = gtid & 31;
    const int d    = warp >> 2;                 // channel row (uniform per warp)
    const int c    = ((warp & 3) << 4) + (lane & 15);  // chunk 0..63
    const int half = lane >> 4;                 // pole half: 0 -> k 0..15, 1 -> k 16..31

    // Output window [32c, 32c+32). Output j maps to series index t = j-1
    // (j = 0 is h_0), so this chunk's series starts at t0 = 32c - 1.
    const float t0f = (float)(CHUNK * c - 1);

    u64 A[KP], B[KP], X[KP], XM[KP];

    #pragma unroll
    for (int kp = 0; kp < KP; kp++) {
        float av[2], bv[2], x0[2], x1[2];
        #pragma unroll
        for (int j = 0; j < 2; j++) {
            const int k = half * 16 + kp * 2 + j;
            const float rv = __ldg(&rr_ [k * DDIM + d]);
            const float tv = __ldg(&th_ [k * DDIM + d]);
            const float Rr = __ldg(&Rre_[k * DDIM + d]);
            const float Ri = __ldg(&Rim_[k * DDIM + d]);

            float sT, cT;
            __sincosf(tv, &sT, &cT);             // arg in [0, 2pi): fast path fine
            const float pre = rv * cT;
            const float pim = rv * sT;
            av[j] = pre + pre;                   // 2 r cos(theta)
            bv[j] = -(rv * rv);                  // -r^2

            // amp = r^t0 via MUFU lg2/ex2. Exponent abs err <= |t0|*2^-22:
            // only meaningful where amp ~1 (small t0) -> <1e-5 output impact.
            const float amp = fast_ex2(t0f * fast_lg2(rv));

            // phase = t0*theta mod 2pi, all-float: exact twoprod, then 2-constant
            // Cody-Waite. Residual ~1e-6 rad.
            const float hi = t0f * tv;
            const float lo = __fmaf_rn(t0f, tv, -hi);     // exact residual
            const float nn = rintf(hi * 0.15915494309f);  // 1/(2pi)
            float red = __fmaf_rn(nn, -6.28125f, hi);     // 2pi hi (13-bit exact)
            red = __fmaf_rn(nn, -1.9353071795864769e-3f, red); // 2pi - 6.28125
            red += lo;
            float sA, cA;
            __sincosf(red, &sA, &cA);

            const float wre = amp * (Rr * cA - Ri * sA);   // Re(R p^t0)
            const float wim = amp * (Rr * sA + Ri * cA);   // Im(R p^t0)
            x0[j] = wre;                                   // x(t0)
            x1[j] = wre * pre - wim * pim;                 // x(t0+1)
        }
        A[kp]  = pk2(av[0], av[1]);
        B[kp]  = pk2(bv[0], bv[1]);
        XM[kp] = pk2(x0[0], x0[1]);
        X[kp]  = pk2(x1[0], x1[1]);
    }

    float* op = out + (size_t)d * LLEN + c * CHUNK;
    const float h0d = __ldg(&h0_[d]);

    #pragma unroll 1
    for (int i = 0; i < CHUNK; i += 4) {
        float buf[4];
        #pragma unroll
        for (int j = 0; j < 4; j++) {
            // partial h(t) over this thread's 8 packed pairs (16 poles)
            u64 s01 = add2(XM[0], XM[1]), s23 = add2(XM[2], XM[3]);
            u64 s45 = add2(XM[4], XM[5]), s67 = add2(XM[6], XM[7]);
            const u64 s = add2(add2(s01, s23), add2(s45, s67));
            float slo, shi; unpk2(s, slo, shi);
            const float part = slo + shi;
            // merge with partner lane (other 16 poles, same chunk)
            const float other = __shfl_xor_sync(0xFFFFFFFFu, part, 16);
            buf[j] = part + other;

            // advance the 16 recurrences (8 packed pairs)
            #pragma unroll
            for (int kp = 0; kp < KP; kp++) {
                const u64 xn = fma2(A[kp], X[kp], mul2(B[kp], XM[kp]));
                XM[kp] = X[kp];
                X[kp]  = xn;
            }
        }
        if (i == 0 && c == 0) buf[0] = h0d;   // output position j=0 is h_0[d]
        if (half == 0) {                      // one lane of the pair stores
            float4 v; v.x = buf[0]; v.y = buf[1]; v.z = buf[2]; v.w = buf[3];
            *reinterpret_cast<float4*>(op + i) = v;   // 16B aligned: 32c + 4i
        }
    }
}

} // namespace

extern "C" void kernel_launch(void* const* d_in, const int* in_sizes, int n_in,
                              void* d_out, int out_size) {
    const float* rr  = (const float*)d_in[0];   // r      (K, D)
    const float* th  = (const float*)d_in[1];   // theta  (K, D)
    const float* Rre = (const float*)d_in[2];   // R_re   (K, D)
    const float* Rim = (const float*)d_in[3];   // R_im   (K, D)
    const float* h0  = (const float*)d_in[4];   // h_0    (1, D)
    (void)in_sizes; (void)n_in; (void)out_size; // shapes fixed: K=32, D=1024, L=2048

    // 1024 rows x 64 chunks x 2 pole-halves = 131072 threads = 4096 warps
    modal_filter_kernel<<<(DDIM * NCH * 2) / 128, 128>>>(
        rr, th, Rre, Rim, h0, (float*)d_out);
}